// round 15
// baseline (speedup 1.0000x reference)
#include <cuda_runtime.h>
#include <cuda_fp16.h>
#include <stdint.h>
#include <math.h>

// ---------------------------------------------------------------- scratch
__device__ float g_vsum[8 * 8 * 32 * 32];     // [b][n][x][y]
__device__ float g_wvsum[8 * 512];
__device__ __half g_xh[8192 * 512];
__device__ __half g_wqh[512 * 512];
__device__ __half g_wkh[512 * 512];

// ---------------------------------------------------------------- helpers
__device__ __forceinline__ uint32_t smem_u32(const void* p) {
    uint32_t a;
    asm("{ .reg .u64 t; cvta.to.shared.u64 t, %1; cvt.u32.u64 %0, t; }" : "=r"(a) : "l"(p));
    return a;
}
__device__ __forceinline__ void ldsm4(uint32_t* r, uint32_t addr) {
    asm volatile("ldmatrix.sync.aligned.m8n8.x4.shared.b16 {%0,%1,%2,%3}, [%4];"
                 : "=r"(r[0]), "=r"(r[1]), "=r"(r[2]), "=r"(r[3]) : "r"(addr));
}
__device__ __forceinline__ void mma16816(float* d, const uint32_t* a, const uint32_t* b) {
    asm volatile(
        "mma.sync.aligned.m16n8k16.row.col.f32.f16.f16.f32 "
        "{%0,%1,%2,%3}, {%4,%5,%6,%7}, {%8,%9}, {%0,%1,%2,%3};"
        : "+f"(d[0]), "+f"(d[1]), "+f"(d[2]), "+f"(d[3])
        : "r"(a[0]), "r"(a[1]), "r"(a[2]), "r"(a[3]), "r"(b[0]), "r"(b[1]));
}
__device__ __forceinline__ void cp_async16(uint32_t dst, const void* src) {
    asm volatile("cp.async.cg.shared.global [%0], [%1], 16;"
                 :: "r"(dst), "l"(__cvta_generic_to_global(src)) : "memory");
}
__device__ __forceinline__ void cp_commit() {
    asm volatile("cp.async.commit_group;" ::: "memory");
}
__device__ __forceinline__ void bar_sync(int id, int cnt) {
    asm volatile("bar.sync %0, %1;" :: "r"(id), "r"(cnt) : "memory");
}
__device__ __forceinline__ void bar_arrive(int id, int cnt) {
    asm volatile("bar.arrive %0, %1;" :: "r"(id), "r"(cnt));
}

// ---------------------------------------------------------------- kernel: prep_w = wvsum + W fp16 cvt
__global__ void prep_w_kernel(const float* __restrict__ wv,
                              const float* __restrict__ wq,
                              const float* __restrict__ wk,
                              __half* __restrict__ wqh,
                              __half* __restrict__ wkh) {
    if (blockIdx.x < 32) {
        __shared__ float part[4][128];
        int n = blockIdx.x >> 2;
        int cloc = threadIdx.x & 127;
        int rg = threadIdx.x >> 7;
        int c = (blockIdx.x & 3) * 128 + cloc;
        const float* base = wv + (size_t)(n * 64 + rg * 16) * 512 + c;
        float s = 0.f;
#pragma unroll 16
        for (int d = 0; d < 16; ++d) s += base[d * 512];
        part[rg][cloc] = s;
        __syncthreads();
        if (rg == 0)
            g_wvsum[n * 512 + c] = part[0][cloc] + part[1][cloc] + part[2][cloc] + part[3][cloc];
        return;
    }
    int i = (blockIdx.x - 32) * 512 + threadIdx.x;
    const float* src;
    __half* dst;
    int j;
    if (i < 65536) { src = wq; dst = wqh; j = i; }
    else           { src = wk; dst = wkh; j = i - 65536; }
    float4 v = ((const float4*)src)[j];
    ((ushort4*)dst)[j] = make_ushort4(
        __half_as_ushort(__float2half(v.x)), __half_as_ushort(__float2half(v.y)),
        __half_as_ushort(__float2half(v.z)), __half_as_ushort(__float2half(v.w)));
}

// ---------------------------------------------------------------- kernel: prep_x = x fp16 cvt + vsum
__global__ void prep_x_kernel(const float* __restrict__ x, __half* __restrict__ xh) {
    int p = blockIdx.x * 8 + (threadIdx.x >> 5);
    int lane = threadIdx.x & 31;
    const float4* xr = (const float4*)(x + (size_t)p * 512);
    float4 xv[4];
#pragma unroll
    for (int t = 0; t < 4; ++t) xv[t] = xr[lane * 4 + t];
    ushort4* xo = (ushort4*)(xh + (size_t)p * 512);
#pragma unroll
    for (int t = 0; t < 4; ++t) {
        xo[lane * 4 + t] = make_ushort4(
            __half_as_ushort(__float2half(xv[t].x)), __half_as_ushort(__float2half(xv[t].y)),
            __half_as_ushort(__float2half(xv[t].z)), __half_as_ushort(__float2half(xv[t].w)));
    }
    float acc[8];
#pragma unroll
    for (int n = 0; n < 8; ++n) {
        const float4* wr = (const float4*)(g_wvsum + n * 512);
        float s = 0.f;
#pragma unroll
        for (int t = 0; t < 4; ++t) {
            float4 w = wr[lane * 4 + t];
            s = fmaf(xv[t].x, w.x, s); s = fmaf(xv[t].y, w.y, s);
            s = fmaf(xv[t].z, w.z, s); s = fmaf(xv[t].w, w.w, s);
        }
#pragma unroll
        for (int o = 16; o > 0; o >>= 1) s += __shfl_xor_sync(0xffffffffu, s, o);
        acc[n] = s;
    }
    if (lane < 8) {
        float v = acc[0];
#pragma unroll
        for (int n = 1; n < 8; ++n) if (lane == n) v = acc[n];
        int b = p >> 10, pos = p & 1023;
        g_vsum[(b * 8 + lane) * 1024 + pos] = v;
    }
}

// ---------------------------------------------------------------- kernel: warp-specialized fused kernel
// block = (128-pixel tile) x (head pair). grid 256 = 64 tiles x 4 pairs; 384 threads, occ 1.
// warps 0-7 compute; warps 8-11 store head0; ALL 12 warps store head1 cooperatively.
static constexpr int RS   = 144;
static constexpr int BUF  = 36864;
static constexpr int XH_O = 0;
static constexpr int QH_O = 18432;
static constexpr int KH_O = 27648;
static constexpr int SM_TOTAL = 2 * BUF;    // 73728 dynamic

__global__ void __launch_bounds__(384, 1)
qk_kernel(float* __restrict__ out) {
    extern __shared__ char smem[];
    __shared__ float  ws[2][128];      // per-head softmax weights
    __shared__ float4 vsmS[2][256];    // per-head vsum rows
    const uint32_t sb = smem_u32(smem);
    const int tid  = threadIdx.x;
    const int lane = tid & 31;
    const int tile = blockIdx.x & 63;
    const int hp   = blockIdx.x >> 6;          // 0..3
    const int pix0 = tile * 128;
    const int b    = pix0 >> 10;
    const int head0 = hp * 2;

    float4* oBase = (float4*)out + ((size_t)(b * 8 + head0) * 1024 + (pix0 & 1023)) * 256;
    float4* oB    = oBase + (size_t)1024 * 256;   // head0+1 slab

    // ================= store warps (tid 256..383) =================
    if (tid >= 256) {
        const int t = tid - 256;                // 0..127
#pragma unroll
        for (int u = 0; u < 2; ++u) {
            const float4* src = (const float4*)(g_vsum + (size_t)(b * 8 + head0 + u) * 1024);
            vsmS[u][t]       = src[t];
            vsmS[u][t + 128] = src[t + 128];
        }
        // head 0: wait for weights, stream 512 KB on 4 warps
        bar_sync(1, 384);
        {
            const float4 v0 = vsmS[0][t];
            const float4 v1 = vsmS[0][t + 128];
#pragma unroll 4
            for (int row = 0; row < 128; ++row) {
                float s = ws[0][row];
                __stcs(oBase + (size_t)row * 256 + t,
                       make_float4(s * v0.x, s * v0.y, s * v0.z, s * v0.w));
                __stcs(oBase + (size_t)row * 256 + t + 128,
                       make_float4(s * v1.x, s * v1.y, s * v1.z, s * v1.w));
            }
        }
        // head 1: cooperative with compute warps
        bar_sync(2, 384);
        const int w12 = tid >> 5;               // 8..11
        for (int row = w12; row < 128; row += 12) {
            float s = ws[1][row];
            float4* orow = oB + (size_t)row * 256;
#pragma unroll
            for (int k = 0; k < 8; ++k) {
                float4 v = vsmS[1][lane + 32 * k];
                __stcs(orow + lane + 32 * k,
                       make_float4(s * v.x, s * v.y, s * v.z, s * v.w));
            }
        }
        return;
    }

    // ================= compute warps (tid 0..255) =================
    const int wid  = tid >> 5;
    const uint32_t a_off = sb + (uint32_t)(wid * 16 + (lane & 15)) * RS + ((lane >> 4) << 4);
    const uint32_t b_row = (lane & 7) + ((lane >> 4) << 3);
    const uint32_t b_off = sb + b_row * RS + (((lane >> 3) & 1) << 4);

    uint32_t xso[4];
    const __half* xgp[4];
#pragma unroll
    for (int g = 0; g < 4; ++g) {
        int idx = tid + g * 256;
        int r = idx >> 3, cc = idx & 7;
        xso[g] = (uint32_t)r * RS + cc * 16;
        xgp[g] = g_xh + (size_t)(pix0 + r) * 512 + cc * 8;
    }
    int wr_[2], wc_[2];
    uint32_t wso[2];
#pragma unroll
    for (int g = 0; g < 2; ++g) {
        int idx = tid + g * 256;
        wr_[g] = idx >> 3; wc_[g] = idx & 7;
        wso[g] = (uint32_t)wr_[g] * RS + wc_[g] * 16;
    }

#pragma unroll 1
    for (int u = 0; u < 2; ++u) {
        const int head = head0 + u;
        const __half *qgp[2], *kgp[2];
#pragma unroll
        for (int g = 0; g < 2; ++g) {
            qgp[g] = g_wqh + (size_t)(head * 64 + wr_[g]) * 512 + wc_[g] * 8;
            kgp[g] = g_wkh + (size_t)(head * 64 + wr_[g]) * 512 + wc_[g] * 8;
        }

        float accQ[8][4], accK[8][4];
#pragma unroll
        for (int i = 0; i < 8; ++i)
#pragma unroll
            for (int j = 0; j < 4; ++j) { accQ[i][j] = 0.f; accK[i][j] = 0.f; }

        // prefetch chunk 0 into buffer 0
        {
            const uint32_t base = sb;
#pragma unroll
            for (int g = 0; g < 4; ++g) cp_async16(base + XH_O + xso[g], xgp[g]);
#pragma unroll
            for (int g = 0; g < 2; ++g) {
                cp_async16(base + QH_O + wso[g], qgp[g]);
                cp_async16(base + KH_O + wso[g], kgp[g]);
            }
            cp_commit();
        }

        for (int ch = 0; ch < 8; ++ch) {
            const uint32_t boff = (uint32_t)(ch & 1) * BUF;
            if (ch < 7) {
                const uint32_t base = sb + ((uint32_t)((ch + 1) & 1) * BUF);
                const int co = (ch + 1) * 64;
#pragma unroll
                for (int g = 0; g < 4; ++g) cp_async16(base + XH_O + xso[g], xgp[g] + co);
#pragma unroll
                for (int g = 0; g < 2; ++g) {
                    cp_async16(base + QH_O + wso[g], qgp[g] + co);
                    cp_async16(base + KH_O + wso[g], kgp[g] + co);
                }
                cp_commit();
                asm volatile("cp.async.wait_group 1;" ::: "memory");
            } else {
                asm volatile("cp.async.wait_group 0;" ::: "memory");
            }
            bar_sync(5, 256);

            const uint32_t ab = a_off + boff;
            const uint32_t bb = b_off + boff;
#pragma unroll
            for (int ks = 0; ks < 4; ++ks) {
                const uint32_t ko = ks * 32;
                uint32_t ah[4];
                ldsm4(ah, ab + XH_O + ko);
#pragma unroll
                for (int np = 0; np < 4; ++np) {
                    const uint32_t off = bb + np * (16 * RS) + ko;
                    uint32_t bq[4], bk[4];
                    ldsm4(bq, off + QH_O);
                    ldsm4(bk, off + KH_O);
                    mma16816(accQ[np * 2],     ah, bq);
                    mma16816(accQ[np * 2 + 1], ah, bq + 2);
                    mma16816(accK[np * 2],     ah, bk);
                    mma16816(accK[np * 2 + 1], ah, bk + 2);
                }
            }
            bar_sync(5, 256);
        }

        // per-pixel logit
        float plo = 0.f, phi = 0.f;
#pragma unroll
        for (int nt = 0; nt < 8; ++nt) {
            plo = fmaf(accQ[nt][0], accK[nt][0], plo);
            plo = fmaf(accQ[nt][1], accK[nt][1], plo);
            phi = fmaf(accQ[nt][2], accK[nt][2], phi);
            phi = fmaf(accQ[nt][3], accK[nt][3], phi);
        }
        plo += __shfl_xor_sync(0xffffffffu, plo, 1);
        plo += __shfl_xor_sync(0xffffffffu, plo, 2);
        phi += __shfl_xor_sync(0xffffffffu, phi, 1);
        phi += __shfl_xor_sync(0xffffffffu, phi, 2);
        if ((lane & 3) == 0) {
            int i0 = wid * 16 + (lane >> 2);
            ws[u][i0] = plo;
            ws[u][i0 + 8] = phi;
        }
        bar_sync(5, 256);

        if (tid < 128) {
            float v = ws[u][tid] * 0.125f;
            float m = v;
#pragma unroll
            for (int o = 16; o > 0; o >>= 1) m = fmaxf(m, __shfl_xor_sync(0xffffffffu, m, o));
            float e = __expf(v - m);
            float s = e;
#pragma unroll
            for (int o = 16; o > 0; o >>= 1) s += __shfl_xor_sync(0xffffffffu, s, o);
            ws[u][tid] = e / s;
        }
        bar_sync(5, 256);
        __threadfence_block();
        if (u == 0) bar_arrive(1, 384);     // release head 0 to store warps
    }

    // head 1: cooperative store with the store warps
    bar_sync(2, 384);
    const int w12 = tid >> 5;               // 0..7
    for (int row = w12; row < 128; row += 12) {
        float s = ws[1][row];
        float4* orow = oB + (size_t)row * 256;
#pragma unroll
        for (int k = 0; k < 8; ++k) {
            float4 v = vsmS[1][lane + 32 * k];
            __stcs(orow + lane + 32 * k,
                   make_float4(s * v.x, s * v.y, s * v.z, s * v.w));
        }
    }
}

// ----------------------------------------------------------------
extern "C" void kernel_launch(void* const* d_in, const int* in_sizes, int n_in,
                              void* d_out, int out_size) {
    const float* x  = (const float*)d_in[0];
    const float* wq = (const float*)d_in[1];
    const float* wk = (const float*)d_in[2];
    const float* wv = (const float*)d_in[3];
    float* out = (float*)d_out;

    cudaFuncSetAttribute(qk_kernel, cudaFuncAttributeMaxDynamicSharedMemorySize, SM_TOTAL);

    __half *xh, *wqh, *wkh;
    cudaGetSymbolAddress((void**)&xh, g_xh);
    cudaGetSymbolAddress((void**)&wqh, g_wqh);
    cudaGetSymbolAddress((void**)&wkh, g_wkh);

    prep_w_kernel<<<288, 512>>>(wv, wq, wk, wqh, wkh);
    prep_x_kernel<<<1024, 256>>>(x, xh);
    qk_kernel<<<256, 384, SM_TOTAL>>>(out);
}

// round 16
// speedup vs baseline: 1.0706x; 1.0706x over previous
#include <cuda_runtime.h>
#include <cuda_fp16.h>
#include <stdint.h>
#include <math.h>

// ---------------------------------------------------------------- scratch
__device__ float g_vsum[8 * 8 * 32 * 32];     // [b][n][x][y]
__device__ float g_wvsum[8 * 512];
__device__ __half g_xh[8192 * 512];
__device__ __half g_wqh[512 * 512];
__device__ __half g_wkh[512 * 512];

// ---------------------------------------------------------------- helpers
__device__ __forceinline__ uint32_t smem_u32(const void* p) {
    uint32_t a;
    asm("{ .reg .u64 t; cvta.to.shared.u64 t, %1; cvt.u32.u64 %0, t; }" : "=r"(a) : "l"(p));
    return a;
}
__device__ __forceinline__ void ldsm4(uint32_t* r, uint32_t addr) {
    asm volatile("ldmatrix.sync.aligned.m8n8.x4.shared.b16 {%0,%1,%2,%3}, [%4];"
                 : "=r"(r[0]), "=r"(r[1]), "=r"(r[2]), "=r"(r[3]) : "r"(addr));
}
__device__ __forceinline__ void mma16816(float* d, const uint32_t* a, const uint32_t* b) {
    asm volatile(
        "mma.sync.aligned.m16n8k16.row.col.f32.f16.f16.f32 "
        "{%0,%1,%2,%3}, {%4,%5,%6,%7}, {%8,%9}, {%0,%1,%2,%3};"
        : "+f"(d[0]), "+f"(d[1]), "+f"(d[2]), "+f"(d[3])
        : "r"(a[0]), "r"(a[1]), "r"(a[2]), "r"(a[3]), "r"(b[0]), "r"(b[1]));
}
__device__ __forceinline__ void cp_async16(uint32_t dst, const void* src) {
    asm volatile("cp.async.cg.shared.global [%0], [%1], 16;"
                 :: "r"(dst), "l"(__cvta_generic_to_global(src)) : "memory");
}
__device__ __forceinline__ void cp_commit() {
    asm volatile("cp.async.commit_group;" ::: "memory");
}
__device__ __forceinline__ void bar_sync(int id, int cnt) {
    asm volatile("bar.sync %0, %1;" :: "r"(id), "r"(cnt) : "memory");
}
__device__ __forceinline__ void bar_arrive(int id, int cnt) {
    asm volatile("bar.arrive %0, %1;" :: "r"(id), "r"(cnt));
}

// ---------------------------------------------------------------- kernel: prep_w = wvsum + W fp16 cvt
__global__ void prep_w_kernel(const float* __restrict__ wv,
                              const float* __restrict__ wq,
                              const float* __restrict__ wk,
                              __half* __restrict__ wqh,
                              __half* __restrict__ wkh) {
    if (blockIdx.x < 32) {
        __shared__ float part[4][128];
        int n = blockIdx.x >> 2;
        int cloc = threadIdx.x & 127;
        int rg = threadIdx.x >> 7;
        int c = (blockIdx.x & 3) * 128 + cloc;
        const float* base = wv + (size_t)(n * 64 + rg * 16) * 512 + c;
        float s = 0.f;
#pragma unroll 16
        for (int d = 0; d < 16; ++d) s += base[d * 512];
        part[rg][cloc] = s;
        __syncthreads();
        if (rg == 0)
            g_wvsum[n * 512 + c] = part[0][cloc] + part[1][cloc] + part[2][cloc] + part[3][cloc];
        return;
    }
    int i = (blockIdx.x - 32) * 512 + threadIdx.x;
    const float* src;
    __half* dst;
    int j;
    if (i < 65536) { src = wq; dst = wqh; j = i; }
    else           { src = wk; dst = wkh; j = i - 65536; }
    float4 v = ((const float4*)src)[j];
    ((ushort4*)dst)[j] = make_ushort4(
        __half_as_ushort(__float2half(v.x)), __half_as_ushort(__float2half(v.y)),
        __half_as_ushort(__float2half(v.z)), __half_as_ushort(__float2half(v.w)));
}

// ---------------------------------------------------------------- kernel: prep_x = x fp16 cvt + vsum
__global__ void prep_x_kernel(const float* __restrict__ x, __half* __restrict__ xh) {
    int p = blockIdx.x * 8 + (threadIdx.x >> 5);
    int lane = threadIdx.x & 31;
    const float4* xr = (const float4*)(x + (size_t)p * 512);
    float4 xv[4];
#pragma unroll
    for (int t = 0; t < 4; ++t) xv[t] = xr[lane * 4 + t];
    ushort4* xo = (ushort4*)(xh + (size_t)p * 512);
#pragma unroll
    for (int t = 0; t < 4; ++t) {
        xo[lane * 4 + t] = make_ushort4(
            __half_as_ushort(__float2half(xv[t].x)), __half_as_ushort(__float2half(xv[t].y)),
            __half_as_ushort(__float2half(xv[t].z)), __half_as_ushort(__float2half(xv[t].w)));
    }
    float acc[8];
#pragma unroll
    for (int n = 0; n < 8; ++n) {
        const float4* wr = (const float4*)(g_wvsum + n * 512);
        float s = 0.f;
#pragma unroll
        for (int t = 0; t < 4; ++t) {
            float4 w = wr[lane * 4 + t];
            s = fmaf(xv[t].x, w.x, s); s = fmaf(xv[t].y, w.y, s);
            s = fmaf(xv[t].z, w.z, s); s = fmaf(xv[t].w, w.w, s);
        }
#pragma unroll
        for (int o = 16; o > 0; o >>= 1) s += __shfl_xor_sync(0xffffffffu, s, o);
        acc[n] = s;
    }
    if (lane < 8) {
        float v = acc[0];
#pragma unroll
        for (int n = 1; n < 8; ++n) if (lane == n) v = acc[n];
        int b = p >> 10, pos = p & 1023;
        g_vsum[(b * 8 + lane) * 1024 + pos] = v;
    }
}

// ---------------------------------------------------------------- persistent warp-specialized kernel
// grid 152 (one/SM), 384 threads, occ 1. Block owns units u = bid + i*152, u < 512.
// unit = (tile = u & 63, head = u >> 6). warps 0-7 compute, 8-11 store; ring-2 slots.
// barriers: full[s] = 1+s (compute arrive 256 / store sync 128)
//           empty[s] = 3+s (store arrive 128 / compute sync 256); compute-internal id 5.
static constexpr int RS   = 144;
static constexpr int BUF  = 36864;
static constexpr int XH_O = 0;
static constexpr int QH_O = 18432;
static constexpr int KH_O = 27648;
static constexpr int SM_TOTAL = 2 * BUF;
static constexpr int NBLK = 152;
static constexpr int NUNIT = 512;

__global__ void __launch_bounds__(384, 1)
qk_kernel(float* __restrict__ out) {
    extern __shared__ char smem[];
    __shared__ float  ws[2][128];
    __shared__ float4 vsmS[2][256];
    const uint32_t sb = smem_u32(smem);
    const int tid  = threadIdx.x;
    const int lane = tid & 31;
    const int bid  = blockIdx.x;
    const int nu   = (bid < NUNIT - 3 * NBLK) ? 4 : 3;   // 512-456=56: bid<56 -> 4 units

    // ================= store warps (tid 256..383) =================
    if (tid >= 256) {
        const int t = tid - 256;                // 0..127
        const int w12 = tid >> 5;               // 8..11
#pragma unroll 1
        for (int i = 0; i < nu; ++i) {
            const int u = bid + i * NBLK;
            const int tile = u & 63, head = u >> 6;
            const int pix0 = tile * 128, b = pix0 >> 10;
            const int s = i & 1;
            const float4* src = (const float4*)(g_vsum + (size_t)(b * 8 + head) * 1024);
            vsmS[s][t]       = src[t];
            vsmS[s][t + 128] = src[t + 128];
            float4* o = (float4*)out + ((size_t)(b * 8 + head) * 1024 + (pix0 & 1023)) * 256;

            bar_sync(1 + s, 384);               // wait full
            if (i == nu - 1) {
                // cooperative store with compute warps
                for (int row = w12; row < 128; row += 12) {
                    float sw = ws[s][row];
                    float4* orow = o + (size_t)row * 256;
#pragma unroll
                    for (int k = 0; k < 8; ++k) {
                        float4 v = vsmS[s][lane + 32 * k];
                        __stcs(orow + lane + 32 * k,
                               make_float4(sw * v.x, sw * v.y, sw * v.z, sw * v.w));
                    }
                }
            } else {
                const float4 v0 = vsmS[s][t];
                const float4 v1 = vsmS[s][t + 128];
#pragma unroll 4
                for (int row = 0; row < 128; ++row) {
                    float sw = ws[s][row];
                    __stcs(o + (size_t)row * 256 + t,
                           make_float4(sw * v0.x, sw * v0.y, sw * v0.z, sw * v0.w));
                    __stcs(o + (size_t)row * 256 + t + 128,
                           make_float4(sw * v1.x, sw * v1.y, sw * v1.z, sw * v1.w));
                }
                bar_arrive(3 + s, 384);         // release slot s
            }
        }
        return;
    }

    // ================= compute warps (tid 0..255) =================
    const int wid  = tid >> 5;
    const uint32_t a_off = sb + (uint32_t)(wid * 16 + (lane & 15)) * RS + ((lane >> 4) << 4);
    const uint32_t b_row = (lane & 7) + ((lane >> 4) << 3);
    const uint32_t b_off = sb + b_row * RS + (((lane >> 3) & 1) << 4);

    // loader patterns (row/col fixed; pointers rebuilt per unit)
    int xr_[4], xc_[4];
    uint32_t xso[4];
#pragma unroll
    for (int g = 0; g < 4; ++g) {
        int idx = tid + g * 256;
        xr_[g] = idx >> 3; xc_[g] = idx & 7;
        xso[g] = (uint32_t)xr_[g] * RS + xc_[g] * 16;
    }
    int wr_[2], wc_[2];
    uint32_t wso[2];
#pragma unroll
    for (int g = 0; g < 2; ++g) {
        int idx = tid + g * 256;
        wr_[g] = idx >> 3; wc_[g] = idx & 7;
        wso[g] = (uint32_t)wr_[g] * RS + wc_[g] * 16;
    }

#pragma unroll 1
    for (int i = 0; i < nu; ++i) {
        const int u = bid + i * NBLK;
        const int tile = u & 63, head = u >> 6;
        const int pix0 = tile * 128;
        const int s = i & 1;

        const __half *xgp[4], *qgp[2], *kgp[2];
#pragma unroll
        for (int g = 0; g < 4; ++g)
            xgp[g] = g_xh + (size_t)(pix0 + xr_[g]) * 512 + xc_[g] * 8;
#pragma unroll
        for (int g = 0; g < 2; ++g) {
            qgp[g] = g_wqh + (size_t)(head * 64 + wr_[g]) * 512 + wc_[g] * 8;
            kgp[g] = g_wkh + (size_t)(head * 64 + wr_[g]) * 512 + wc_[g] * 8;
        }

        float accQ[8][4], accK[8][4];
#pragma unroll
        for (int a = 0; a < 8; ++a)
#pragma unroll
            for (int j = 0; j < 4; ++j) { accQ[a][j] = 0.f; accK[a][j] = 0.f; }

        // prefetch chunk 0 into buffer 0
        {
            const uint32_t base = sb;
#pragma unroll
            for (int g = 0; g < 4; ++g) cp_async16(base + XH_O + xso[g], xgp[g]);
#pragma unroll
            for (int g = 0; g < 2; ++g) {
                cp_async16(base + QH_O + wso[g], qgp[g]);
                cp_async16(base + KH_O + wso[g], kgp[g]);
            }
            cp_commit();
        }

        for (int ch = 0; ch < 8; ++ch) {
            const uint32_t boff = (uint32_t)(ch & 1) * BUF;
            if (ch < 7) {
                const uint32_t base = sb + ((uint32_t)((ch + 1) & 1) * BUF);
                const int co = (ch + 1) * 64;
#pragma unroll
                for (int g = 0; g < 4; ++g) cp_async16(base + XH_O + xso[g], xgp[g] + co);
#pragma unroll
                for (int g = 0; g < 2; ++g) {
                    cp_async16(base + QH_O + wso[g], qgp[g] + co);
                    cp_async16(base + KH_O + wso[g], kgp[g] + co);
                }
                cp_commit();
                asm volatile("cp.async.wait_group 1;" ::: "memory");
            } else {
                asm volatile("cp.async.wait_group 0;" ::: "memory");
            }
            bar_sync(5, 256);

            const uint32_t ab = a_off + boff;
            const uint32_t bb = b_off + boff;
#pragma unroll
            for (int ks = 0; ks < 4; ++ks) {
                const uint32_t ko = ks * 32;
                uint32_t ah[4];
                ldsm4(ah, ab + XH_O + ko);
#pragma unroll
                for (int np = 0; np < 4; ++np) {
                    const uint32_t off = bb + np * (16 * RS) + ko;
                    uint32_t bq[4], bk[4];
                    ldsm4(bq, off + QH_O);
                    ldsm4(bk, off + KH_O);
                    mma16816(accQ[np * 2],     ah, bq);
                    mma16816(accQ[np * 2 + 1], ah, bq + 2);
                    mma16816(accK[np * 2],     ah, bk);
                    mma16816(accK[np * 2 + 1], ah, bk + 2);
                }
            }
            bar_sync(5, 256);
        }

        // per-pixel logit
        float plo = 0.f, phi = 0.f;
#pragma unroll
        for (int nt = 0; nt < 8; ++nt) {
            plo = fmaf(accQ[nt][0], accK[nt][0], plo);
            plo = fmaf(accQ[nt][1], accK[nt][1], plo);
            phi = fmaf(accQ[nt][2], accK[nt][2], phi);
            phi = fmaf(accQ[nt][3], accK[nt][3], phi);
        }
        plo += __shfl_xor_sync(0xffffffffu, plo, 1);
        plo += __shfl_xor_sync(0xffffffffu, plo, 2);
        phi += __shfl_xor_sync(0xffffffffu, phi, 1);
        phi += __shfl_xor_sync(0xffffffffu, phi, 2);

        if (i >= 2) bar_sync(3 + s, 384);      // slot s free?
        if ((lane & 3) == 0) {
            int i0 = wid * 16 + (lane >> 2);
            ws[s][i0] = plo;
            ws[s][i0 + 8] = phi;
        }
        bar_sync(5, 256);

        if (tid < 128) {
            float v = ws[s][tid] * 0.125f;
            float m = v;
#pragma unroll
            for (int o = 16; o > 0; o >>= 1) m = fmaxf(m, __shfl_xor_sync(0xffffffffu, m, o));
            float e = __expf(v - m);
            float sm = e;
#pragma unroll
            for (int o = 16; o > 0; o >>= 1) sm += __shfl_xor_sync(0xffffffffu, sm, o);
            ws[s][tid] = e / sm;
        }
        bar_sync(5, 256);
        __threadfence_block();

        if (i == nu - 1) {
            // joint barrier, then cooperative store of the last unit
            bar_sync(1 + s, 384);
            const int b2 = pix0 >> 10;
            float4* o = (float4*)out + ((size_t)(b2 * 8 + head) * 1024 + (pix0 & 1023)) * 256;
            for (int row = wid; row < 128; row += 12) {
                float sw = ws[s][row];
                float4* orow = o + (size_t)row * 256;
#pragma unroll
                for (int k = 0; k < 8; ++k) {
                    float4 v = vsmS[s][lane + 32 * k];
                    __stcs(orow + lane + 32 * k,
                           make_float4(sw * v.x, sw * v.y, sw * v.z, sw * v.w));
                }
            }
        } else {
            bar_arrive(1 + s, 384);            // release head to store warps
        }
    }
}

// ----------------------------------------------------------------
extern "C" void kernel_launch(void* const* d_in, const int* in_sizes, int n_in,
                              void* d_out, int out_size) {
    const float* x  = (const float*)d_in[0];
    const float* wq = (const float*)d_in[1];
    const float* wk = (const float*)d_in[2];
    const float* wv = (const float*)d_in[3];
    float* out = (float*)d_out;

    cudaFuncSetAttribute(qk_kernel, cudaFuncAttributeMaxDynamicSharedMemorySize, SM_TOTAL);

    __half *xh, *wqh, *wkh;
    cudaGetSymbolAddress((void**)&xh, g_xh);
    cudaGetSymbolAddress((void**)&wqh, g_wqh);
    cudaGetSymbolAddress((void**)&wkh, g_wkh);

    prep_w_kernel<<<288, 512>>>(wv, wq, wk, wqh, wkh);
    prep_x_kernel<<<1024, 256>>>(x, xh);
    qk_kernel<<<NBLK, 384, SM_TOTAL>>>(out);
}